// round 8
// baseline (speedup 1.0000x reference)
#include <cuda_runtime.h>

typedef unsigned long long u64;
typedef unsigned int u32;

#define B_ 2048
#define I_ 512
#define O_ 256
#define BM 16            // batch rows per block
#define OT 128           // output cols per block
#define KSPL 4           // split-K factor
#define IB (I_ / KSPL)   // 128 i's per block
#define NTH 64

// Split-K partial products: part_g[ks][b][o]
__device__ float part_g[KSPL * B_ * O_];

__device__ __forceinline__ u64 fma2_(u64 a, u64 b, u64 c) {
    u64 d;
    asm("fma.rn.f32x2 %0, %1, %2, %3;" : "=l"(d) : "l"(a), "l"(b), "l"(c));
    return d;
}
__device__ __forceinline__ u64 mul2_(u64 a, u64 b) {
    u64 d;
    asm("mul.rn.f32x2 %0, %1, %2;" : "=l"(d) : "l"(a), "l"(b));
    return d;
}

// ---------------- main: one block = (ks, b-tile, o-half) ----------------
__global__ __launch_bounds__(NTH, 12) void l0conj_main(
    const float* __restrict__ x,      // [B_, I_]
    const float* __restrict__ w,      // [I_, O_]
    const float* __restrict__ qz)     // [I_]
{
    __shared__ __align__(16) float zsm[IB];           // 512B
    __shared__ __align__(16) float aPd[IB * 2 * BM];  // 16KB: aPd[i*32+2b]=aPd[i*32+2b+1]=x[b][i]*z[i]-1

    const int tid = threadIdx.x;
    const int ks = blockIdx.x & (KSPL - 1);
    const int ot = (blockIdx.x >> 2) & 1;
    const int bt = blockIdx.x >> 3;
    const int i0 = ks * IB;
    const int os = ot * OT;
    const int b0 = bt * BM;

    // z for this block's i-range
    {
        float q0 = qz[i0 + 2 * tid];
        float q1 = qz[i0 + 2 * tid + 1];
        float p0 = 1.0f / (1.0f + expf(-q0));
        float p1 = 1.0f / (1.0f + expf(-q1));
        zsm[2 * tid]     = fminf(fmaxf(fmaf(p0, 1.2f, -0.1f), 0.0f), 1.0f);
        zsm[2 * tid + 1] = fminf(fmaxf(fmaf(p1, 1.2f, -0.1f), 0.0f), 1.0f);
    }
    __syncthreads();

    // a = x*z - 1 into aPd[i][2b] duplicated (so LDS.128 yields f32x2 dup-pairs).
    // Thread: row r = tid&15, i-chunk ic = tid>>4 (32 i's each).
    {
        const int r = tid & 15;
        const int ic = tid >> 4;
        const float* xrow = x + (b0 + r) * I_ + i0 + ic * 32;
        const float* zc = zsm + ic * 32;
        float2* ac = (float2*)(aPd + ic * 32 * (2 * BM) + 2 * r);
#pragma unroll
        for (int j4 = 0; j4 < 8; ++j4) {
            float4 xv = *(const float4*)(xrow + j4 * 4);
            float4 zv = *(const float4*)(zc + j4 * 4);
            float v0 = fmaf(xv.x, zv.x, -1.0f);
            float v1 = fmaf(xv.y, zv.y, -1.0f);
            float v2 = fmaf(xv.z, zv.z, -1.0f);
            float v3 = fmaf(xv.w, zv.w, -1.0f);
            ac[(j4 * 4 + 0) * BM] = make_float2(v0, v0);
            ac[(j4 * 4 + 1) * BM] = make_float2(v1, v1);
            ac[(j4 * 4 + 2) * BM] = make_float2(v2, v2);
            ac[(j4 * 4 + 3) * BM] = make_float2(v3, v3);
        }
    }
    __syncthreads();

    // Thread tile: 4 batch rows x 8 o's (4 o-pair accumulator columns).
    const int og = tid & 15;          // o-offset = og*8
    const int bth = (tid >> 4) * 4;   // rows bth..bth+3

    const u64 one2 = 0x3F8000003F800000ULL;
    u64 p[4][4];
#pragma unroll
    for (int r = 0; r < 4; ++r)
#pragma unroll
        for (int c = 0; c < 4; ++c) p[r][c] = one2;

    const float* aB = aPd + 2 * bth;
    const float* wgp = w + i0 * O_ + os + og * 8;   // + i*O_

    // Mainloop: pure LDS + streaming LDG + packed fma. No barriers, no cp.async.
    // unroll 4 -> 8 LDG.128 batched ahead per group (covers L2 latency with
    // ~6 warps/SMSP of occupancy on top).
#pragma unroll 4
    for (int i = 0; i < IB; ++i) {
        const ulonglong2* ap = (const ulonglong2*)(aB + i * (2 * BM));
        ulonglong2 a01 = ap[0];                               // (b,b),(b+1,b+1)
        ulonglong2 a23 = ap[1];                               // (b+2,b+2),(b+3,b+3)
        ulonglong2 w01 = *(const ulonglong2*)(wgp + i * O_);      // (o,o+1),(o+2,o+3)
        ulonglong2 w23 = *(const ulonglong2*)(wgp + i * O_ + 4);  // (o+4..o+7)
        u64 ad[4] = {a01.x, a01.y, a23.x, a23.y};
        u64 wv[4] = {w01.x, w01.y, w23.x, w23.y};
#pragma unroll
        for (int r = 0; r < 4; ++r)
#pragma unroll
            for (int c = 0; c < 4; ++c)
                p[r][c] = mul2_(p[r][c], fma2_(ad[r], wv[c], one2));
    }

    // Write this split's partial: part_g[ks][b][o..o+7]
    float* pg = part_g + ks * (B_ * O_) + (b0 + bth) * O_ + os + og * 8;
#pragma unroll
    for (int r = 0; r < 4; ++r) {
        *(ulonglong2*)(pg + r * O_)     = make_ulonglong2(p[r][0], p[r][1]);
        *(ulonglong2*)(pg + r * O_ + 4) = make_ulonglong2(p[r][2], p[r][3]);
    }
}

// ---------------- combine: out = prod of 4 partials ----------------
__global__ __launch_bounds__(256) void l0conj_combine(float* __restrict__ out)
{
    const int t0 = (blockIdx.x * 256 + threadIdx.x) * 2;   // 2 float4s per thread
    const float4* p0 = (const float4*)part_g;
    const int ts = B_ * O_ / 4;
#pragma unroll
    for (int j = 0; j < 2; ++j) {
        int t = t0 + j;
        float4 a = p0[t];
        float4 b = p0[t + ts];
        float4 c = p0[t + 2 * ts];
        float4 d = p0[t + 3 * ts];
        float4 r;
        r.x = a.x * b.x * c.x * d.x;
        r.y = a.y * b.y * c.y * d.y;
        r.z = a.z * b.z * c.z * d.z;
        r.w = a.w * b.w * c.w * d.w;
        ((float4*)out)[t] = r;
    }
}

extern "C" void kernel_launch(void* const* d_in, const int* in_sizes, int n_in,
                              void* d_out, int out_size) {
    const float* x = nullptr;
    const float* w = nullptr;
    const float* qz = nullptr;
    for (int i = 0; i < n_in; ++i) {
        if (in_sizes[i] == B_ * I_)      x  = (const float*)d_in[i];
        else if (in_sizes[i] == I_ * O_) w  = (const float*)d_in[i];
        else if (in_sizes[i] == I_)      qz = (const float*)d_in[i];
    }
    l0conj_main<<<KSPL * (B_ / BM) * (O_ / OT), NTH>>>(x, w, qz);
    l0conj_combine<<<(B_ * O_ / 4) / 2 / 256, 256>>>((float*)d_out);
}

// round 9
// speedup vs baseline: 1.0716x; 1.0716x over previous
#include <cuda_runtime.h>

typedef unsigned long long u64;
typedef unsigned int u32;

#define B_ 2048
#define I_ 512
#define O_ 256
#define BM 16            // batch rows per tile (cluster)
#define OT 64            // output cols per tile (cluster)
#define KSPL 4           // split-K = cluster size
#define IB (I_ / KSPL)   // 128 i's per CTA
#define NTH 64

__device__ __forceinline__ u64 fma2_(u64 a, u64 b, u64 c) {
    u64 d;
    asm("fma.rn.f32x2 %0, %1, %2, %3;" : "=l"(d) : "l"(a), "l"(b), "l"(c));
    return d;
}
__device__ __forceinline__ u64 mul2_(u64 a, u64 b) {
    u64 d;
    asm("mul.rn.f32x2 %0, %1, %2;" : "=l"(d) : "l"(a), "l"(b));
    return d;
}

__global__ __launch_bounds__(NTH) __cluster_dims__(KSPL, 1, 1)
void l0conj_main(
    const float* __restrict__ x,      // [B_, I_]
    const float* __restrict__ w,      // [I_, O_]
    const float* __restrict__ qz,     // [I_]
    float* __restrict__ out)          // [B_, O_]
{
    __shared__ __align__(16) float zsm[IB];           // 512B
    __shared__ __align__(16) float aPd[IB * 2 * BM];  // 16KB: aPd[i*32+2b]=aPd[i*32+2b+1]=x[b][i]*z[i]-1
    __shared__ __align__(16) float psm[BM * OT];      // 4KB: this split's partial tile

    const int tid = threadIdx.x;
    u32 rank;
    asm("mov.u32 %0, %%cluster_ctarank;" : "=r"(rank));   // = i-split index
    const int cid = blockIdx.x >> 2;        // 512 clusters
    const int ot = cid & 3;                 // 4 o-slices
    const int bt = cid >> 2;                // 128 b-tiles
    const int i0 = (int)rank * IB;
    const int os = ot * OT;
    const int b0 = bt * BM;

    // z for this CTA's i-range
    {
        float q0 = qz[i0 + 2 * tid];
        float q1 = qz[i0 + 2 * tid + 1];
        float p0 = 1.0f / (1.0f + expf(-q0));
        float p1 = 1.0f / (1.0f + expf(-q1));
        zsm[2 * tid]     = fminf(fmaxf(fmaf(p0, 1.2f, -0.1f), 0.0f), 1.0f);
        zsm[2 * tid + 1] = fminf(fmaxf(fmaf(p1, 1.2f, -0.1f), 0.0f), 1.0f);
    }
    __syncthreads();

    // a = x*z - 1 into aPd duplicated (LDS.128 -> two f32x2 dup-pairs).
    // Thread: row r = tid&15, i-chunk ic = tid>>4 (32 i's each).
    {
        const int r = tid & 15;
        const int ic = tid >> 4;
        const float* xrow = x + (b0 + r) * I_ + i0 + ic * 32;
        const float* zc = zsm + ic * 32;
        float2* ac = (float2*)(aPd + ic * 32 * (2 * BM) + 2 * r);
#pragma unroll
        for (int j4 = 0; j4 < 8; ++j4) {
            float4 xv = *(const float4*)(xrow + j4 * 4);
            float4 zv = *(const float4*)(zc + j4 * 4);
            float v0 = fmaf(xv.x, zv.x, -1.0f);
            float v1 = fmaf(xv.y, zv.y, -1.0f);
            float v2 = fmaf(xv.z, zv.z, -1.0f);
            float v3 = fmaf(xv.w, zv.w, -1.0f);
            ac[(j4 * 4 + 0) * BM] = make_float2(v0, v0);
            ac[(j4 * 4 + 1) * BM] = make_float2(v1, v1);
            ac[(j4 * 4 + 2) * BM] = make_float2(v2, v2);
            ac[(j4 * 4 + 3) * BM] = make_float2(v3, v3);
        }
    }
    __syncthreads();

    // Thread tile: 4 batch rows x 4 o's (2 o-pair accumulator columns).
    const int og = tid & 15;          // o-offset = og*4
    const int bth = (tid >> 4) * 4;   // rows bth..bth+3

    const u64 one2 = 0x3F8000003F800000ULL;
    u64 p[4][2];
#pragma unroll
    for (int r = 0; r < 4; ++r) { p[r][0] = one2; p[r][1] = one2; }

    const float* aB = aPd + 2 * bth;
    const float* wgp = w + i0 * O_ + os + og * 4;   // + i*O_

    // Mainloop: LDS (broadcast) + streaming LDG.128 + packed fma. No barriers.
#pragma unroll 4
    for (int i = 0; i < IB; ++i) {
        const ulonglong2* ap = (const ulonglong2*)(aB + i * (2 * BM));
        ulonglong2 a01 = ap[0];                              // (b,b),(b+1,b+1)
        ulonglong2 a23 = ap[1];                              // (b+2,b+2),(b+3,b+3)
        ulonglong2 wv = *(const ulonglong2*)(wgp + i * O_);  // (o,o+1),(o+2,o+3)
        u64 ad[4] = {a01.x, a01.y, a23.x, a23.y};
#pragma unroll
        for (int r = 0; r < 4; ++r) {
            p[r][0] = mul2_(p[r][0], fma2_(ad[r], wv.x, one2));
            p[r][1] = mul2_(p[r][1], fma2_(ad[r], wv.y, one2));
        }
    }

    // Publish this split's partial tile into OWN smem.
#pragma unroll
    for (int r = 0; r < 4; ++r)
        *(ulonglong2*)(psm + (bth + r) * OT + og * 4) = make_ulonglong2(p[r][0], p[r][1]);

    // Cluster barrier: orders all CTAs' psm writes before peer DSMEM reads.
    asm volatile("barrier.cluster.arrive.aligned;" ::: "memory");
    asm volatile("barrier.cluster.wait.aligned;" ::: "memory");

    // Combine: rank handles rows [rank*4, rank*4+4). Fixed pk order -> deterministic.
    {
        const int r = (int)rank * 4 + (tid >> 4);
        const int c = (tid & 15) * 4;
        const int off = r * OT + c;
        const u32 lp = (u32)__cvta_generic_to_shared(psm + off);

        float4 acc = make_float4(1.f, 1.f, 1.f, 1.f);
#pragma unroll
        for (int pk = 0; pk < KSPL; ++pk) {
            float4 v;
            if (pk == (int)rank) {
                v = *(const float4*)(psm + off);
            } else {
                u32 rp;
                asm("mapa.shared::cluster.u32 %0, %1, %2;" : "=r"(rp) : "r"(lp), "r"(pk));
                asm("ld.shared::cluster.v4.f32 {%0, %1, %2, %3}, [%4];"
                    : "=f"(v.x), "=f"(v.y), "=f"(v.z), "=f"(v.w) : "r"(rp));
            }
            acc.x *= v.x; acc.y *= v.y; acc.z *= v.z; acc.w *= v.w;
        }
        *(float4*)(out + (b0 + r) * O_ + os + c) = acc;
    }

    // No CTA may exit while peers might still read its psm.
    asm volatile("barrier.cluster.arrive.aligned;" ::: "memory");
    asm volatile("barrier.cluster.wait.aligned;" ::: "memory");
}

extern "C" void kernel_launch(void* const* d_in, const int* in_sizes, int n_in,
                              void* d_out, int out_size) {
    const float* x = nullptr;
    const float* w = nullptr;
    const float* qz = nullptr;
    for (int i = 0; i < n_in; ++i) {
        if (in_sizes[i] == B_ * I_)      x  = (const float*)d_in[i];
        else if (in_sizes[i] == I_ * O_) w  = (const float*)d_in[i];
        else if (in_sizes[i] == I_)      qz = (const float*)d_in[i];
    }
    l0conj_main<<<KSPL * (B_ / BM) * (O_ / OT), NTH>>>(x, w, qz, (float*)d_out);
}

// round 10
// speedup vs baseline: 1.1125x; 1.0381x over previous
#include <cuda_runtime.h>

typedef unsigned long long u64;
typedef unsigned int u32;

#define B_ 2048
#define I_ 512
#define O_ 256
#define BM 16            // batch rows per block
#define OT 128           // output cols per block
#define KSPL 4           // split-K factor
#define IB (I_ / KSPL)   // 128 i's per block
#define NTH 64
#define KG 4             // i's per cp.async commit group
#define NG (IB / KG)     // 32 groups
#define RG 8             // ring capacity in groups (16KB)
#define PF 6             // groups committed ahead (distance 5 after wait)
#define NTILES ((B_ / BM) * (O_ / OT))   // 256

// Split-K partial products: part_g[ks][b][o]; per-tile arrival counters.
__device__ float part_g[KSPL * B_ * O_];
__device__ u32 tile_cnt[NTILES];   // zero-init; self-resetting each launch

__device__ __forceinline__ u64 fma2_(u64 a, u64 b, u64 c) {
    u64 d;
    asm("fma.rn.f32x2 %0, %1, %2, %3;" : "=l"(d) : "l"(a), "l"(b), "l"(c));
    return d;
}
__device__ __forceinline__ u64 mul2_(u64 a, u64 b) {
    u64 d;
    asm("mul.rn.f32x2 %0, %1, %2;" : "=l"(d) : "l"(a), "l"(b));
    return d;
}
__device__ __forceinline__ u64 dup2_(float a) {
    u64 d;
    asm("mov.b64 %0, {%1, %1};" : "=l"(d) : "f"(a));
    return d;
}
__device__ __forceinline__ void cpa16(u32 saddr, const void* g) {
    asm volatile("cp.async.cg.shared.global [%0], [%1], 16;" :: "r"(saddr), "l"(g));
}
__device__ __forceinline__ void cpa_commit() { asm volatile("cp.async.commit_group;"); }
__device__ __forceinline__ void cpa_wait5()  { asm volatile("cp.async.wait_group 5;"); }

// L2-direct load: bypasses L1, so no L1 flush/fence is ever needed to see
// partials published by other SMs.
__device__ __forceinline__ float4 ldcg4(const float4* p) {
    float4 v;
    asm volatile("ld.global.cg.v4.f32 {%0, %1, %2, %3}, [%4];"
                 : "=f"(v.x), "=f"(v.y), "=f"(v.z), "=f"(v.w) : "l"(p));
    return v;
}

// ---------------- main: one block = (ks, b-tile, o-half) ----------------
__global__ __launch_bounds__(NTH) void l0conj_main(
    const float* __restrict__ x,      // [B_, I_]
    const float* __restrict__ w,      // [I_, O_]
    const float* __restrict__ qz,     // [I_]
    float* __restrict__ out)          // [B_, O_]
{
    __shared__ __align__(16) float zsm[IB];              // 512B
    __shared__ __align__(16) float aP[IB * BM];          // 8KB  aP[i][b] = x[b][i]*z[i]-1
    __shared__ __align__(16) float wring[RG * KG * OT];  // 16KB
    __shared__ int lastFlag;

    const int tid = threadIdx.x;
    const int ks = blockIdx.x & (KSPL - 1);
    const int ot = (blockIdx.x >> 2) & 1;
    const int bt = blockIdx.x >> 3;
    const int i0 = ks * IB;
    const int os = ot * OT;
    const int b0 = bt * BM;
    const int tile = bt * 2 + ot;

    const u32 wsm = (u32)__cvta_generic_to_shared(wring);
    const float* wg = w + i0 * O_ + os;   // + i*O_ + col

    // Prefetch one group = KG slabs (KG*OT f32 = 2KB = 128 x 16B chunks);
    // thread copies chunks tid and tid+64.
#define PREFW(gsrc, gslot)                                                   \
    {                                                                        \
        _Pragma("unroll") for (int h = 0; h < 2; ++h) {                      \
            int c = tid + 64 * h;                                            \
            int s = c >> 5;                                                  \
            int off = c & 31;                                                \
            cpa16(wsm + (u32)((((gslot) * KG + s) * OT + off * 4) * 4),      \
                  wg + ((gsrc) * KG + s) * O_ + off * 4);                    \
        }                                                                    \
        cpa_commit();                                                        \
    }

    // Fill PF groups up front so L2 latency overlaps the prologue.
#pragma unroll
    for (int g = 0; g < PF; ++g) PREFW(g, g);

    // z for this block's i-range
    {
        float q0 = qz[i0 + 2 * tid];
        float q1 = qz[i0 + 2 * tid + 1];
        float p0 = 1.0f / (1.0f + expf(-q0));
        float p1 = 1.0f / (1.0f + expf(-q1));
        zsm[2 * tid]     = fminf(fmaxf(fmaf(p0, 1.2f, -0.1f), 0.0f), 1.0f);
        zsm[2 * tid + 1] = fminf(fmaxf(fmaf(p1, 1.2f, -0.1f), 0.0f), 1.0f);
    }
    __syncthreads();

    // a = x*z - 1 into aP[i][b]. Thread: row r = tid&15, i-chunk ic = tid>>4 (32 i's).
    {
        const int r = tid & 15;
        const int ic = tid >> 4;
        const float* xrow = x + (b0 + r) * I_ + i0 + ic * 32;
        const float* zc = zsm + ic * 32;
        float* ac = aP + ic * 32 * BM + r;
#pragma unroll
        for (int j4 = 0; j4 < 8; ++j4) {
            float4 xv = *(const float4*)(xrow + j4 * 4);
            float4 zv = *(const float4*)(zc + j4 * 4);
            ac[(j4 * 4 + 0) * BM] = fmaf(xv.x, zv.x, -1.0f);
            ac[(j4 * 4 + 1) * BM] = fmaf(xv.y, zv.y, -1.0f);
            ac[(j4 * 4 + 2) * BM] = fmaf(xv.z, zv.z, -1.0f);
            ac[(j4 * 4 + 3) * BM] = fmaf(xv.w, zv.w, -1.0f);
        }
    }
    __syncthreads();

    // Thread tile: 4 batch rows x 8 o's (4 o-pair accumulator columns).
    const int og = tid & 15;          // o-offset = og*8
    const int bth = (tid >> 4) * 4;   // rows bth..bth+3

    const u64 one2 = 0x3F8000003F800000ULL;
    u64 p[4][4];
#pragma unroll
    for (int r = 0; r < 4; ++r)
#pragma unroll
        for (int c = 0; c < 4; ++c) p[r][c] = one2;

    const float* aB = aP + bth;
    const float* wB = wring + og * 8;

#pragma unroll 1
    for (int g = 0; g < NG; ++g) {
        // Race-free protocol (proven R6):
        //   wait_group 5 -> this thread's commits through group g landed;
        //   __syncthreads -> all threads waited => all of group g visible,
        //                    and all threads finished compute through g-1.
        // Prefetch slot (g+PF)&7 last held group g-2: safe to overwrite.
        cpa_wait5();
        __syncthreads();

        const int gslot = g & (RG - 1);
#pragma unroll
        for (int u = 0; u < KG; ++u) {
            const int i = g * KG + u;
            float4 av = *(const float4*)(aB + i * BM);            // rows bth..bth+3
            const float* ws = wB + (gslot * KG + u) * OT;
            ulonglong2 w01 = *(const ulonglong2*)(ws);            // (o,o+1),(o+2,o+3)
            ulonglong2 w23 = *(const ulonglong2*)(ws + 4);        // (o+4..o+7)
            u64 ad[4] = {dup2_(av.x), dup2_(av.y), dup2_(av.z), dup2_(av.w)};
            u64 wv[4] = {w01.x, w01.y, w23.x, w23.y};
#pragma unroll
            for (int r = 0; r < 4; ++r)
#pragma unroll
                for (int c = 0; c < 4; ++c)
                    p[r][c] = mul2_(p[r][c], fma2_(ad[r], wv[c], one2));
        }

        PREFW((g + PF) & (NG - 1), (g + PF) & (RG - 1));  // tail wraps: fetched, never used
    }

    // Write this split's partial: part_g[ks][b][o..o+7]
    float* pg = part_g + ks * (B_ * O_) + (b0 + bth) * O_ + os + og * 8;
#pragma unroll
    for (int r = 0; r < 4; ++r) {
        *(ulonglong2*)(pg + r * O_)     = make_ulonglong2(p[r][0], p[r][1]);
        *(ulonglong2*)(pg + r * O_ + 4) = make_ulonglong2(p[r][2], p[r][3]);
    }

    // Fence-free publish: barrier composes each thread's stores into tid0's
    // release-atomic (happens-before chain); the last arrival acquires all
    // four splits' partials. NO __threadfence -> no CCTL.IVALL L1 flush.
    __syncthreads();
    if (tid == 0) {
        u32 old;
        asm volatile("atom.global.add.acq_rel.gpu.u32 %0, [%1], %2;"
                     : "=r"(old) : "l"(&tile_cnt[tile]), "r"(1u) : "memory");
        lastFlag = (old == KSPL - 1);
    }
    __syncthreads();

    if (lastFlag) {
        // Combine this 16x128 tile: 512 float4s, 8 per thread, L2-direct reads,
        // fixed split order -> deterministic.
        const float4* s0 = (const float4*)part_g;
        const int ts = B_ * O_ / 4;
#pragma unroll
        for (int j = 0; j < 8; ++j) {
            int idx = tid + 64 * j;             // 0..511
            int r = idx >> 5;                   // row 0..15
            int c = idx & 31;                   // float4 col 0..31
            int off = ((b0 + r) * O_ + os) / 4 + c;
            float4 a = ldcg4(s0 + off);
            float4 b = ldcg4(s0 + off + ts);
            float4 cc = ldcg4(s0 + off + 2 * ts);
            float4 d = ldcg4(s0 + off + 3 * ts);
            float4 v;
            v.x = a.x * b.x * cc.x * d.x;
            v.y = a.y * b.y * cc.y * d.y;
            v.z = a.z * b.z * cc.z * d.z;
            v.w = a.w * b.w * cc.w * d.w;
            ((float4*)out)[off] = v;
        }
        if (tid == 0) atomicExch(&tile_cnt[tile], 0u);  // reset for next replay
    }
}

extern "C" void kernel_launch(void* const* d_in, const int* in_sizes, int n_in,
                              void* d_out, int out_size) {
    const float* x = nullptr;
    const float* w = nullptr;
    const float* qz = nullptr;
    for (int i = 0; i < n_in; ++i) {
        if (in_sizes[i] == B_ * I_)      x  = (const float*)d_in[i];
        else if (in_sizes[i] == I_ * O_) w  = (const float*)d_in[i];
        else if (in_sizes[i] == I_)      qz = (const float*)d_in[i];
    }
    l0conj_main<<<KSPL * (B_ / BM) * (O_ / OT), NTH>>>(x, w, qz, (float*)d_out);
}

// round 11
// speedup vs baseline: 1.1969x; 1.0759x over previous
#include <cuda_runtime.h>

typedef unsigned long long u64;
typedef unsigned int u32;

#define B_ 2048
#define I_ 512
#define O_ 256
#define BM 16            // batch rows per block
#define OT 128           // output cols per block
#define KSPL 4           // split-K factor
#define IB (I_ / KSPL)   // 128 i's per block
#define NTH 128
#define KG 4             // i's per cp.async commit group
#define NG (IB / KG)     // 32 groups
#define RG 8             // ring capacity in groups (16KB)
#define PF 6             // groups committed ahead (distance 5 after wait)

// Split-K partial products: part_g[ks][b][o]
__device__ float part_g[KSPL * B_ * O_];

__device__ __forceinline__ u64 fma2_(u64 a, u64 b, u64 c) {
    u64 d;
    asm("fma.rn.f32x2 %0, %1, %2, %3;" : "=l"(d) : "l"(a), "l"(b), "l"(c));
    return d;
}
__device__ __forceinline__ u64 mul2_(u64 a, u64 b) {
    u64 d;
    asm("mul.rn.f32x2 %0, %1, %2;" : "=l"(d) : "l"(a), "l"(b));
    return d;
}
__device__ __forceinline__ void cpa16(u32 saddr, const void* g) {
    asm volatile("cp.async.cg.shared.global [%0], [%1], 16;" :: "r"(saddr), "l"(g));
}
__device__ __forceinline__ void cpa_commit() { asm volatile("cp.async.commit_group;"); }
__device__ __forceinline__ void cpa_wait5()  { asm volatile("cp.async.wait_group 5;"); }

// ---------------- main: one block = (ks, b-tile, o-half) ----------------
__global__ __launch_bounds__(NTH, 7) void l0conj_main(
    const float* __restrict__ x,      // [B_, I_]
    const float* __restrict__ w,      // [I_, O_]
    const float* __restrict__ qz)     // [I_]
{
    __shared__ __align__(16) float zsm[IB];              // 512B
    __shared__ __align__(16) float aPd[IB * 2 * BM];     // 16KB: aPd[i*32+2b]=aPd[i*32+2b+1]=x[b][i]*z[i]-1
    __shared__ __align__(16) float wring[RG * KG * OT];  // 16KB

    const int tid = threadIdx.x;
    const int ks = blockIdx.x & (KSPL - 1);
    const int ot = (blockIdx.x >> 2) & 1;
    const int bt = blockIdx.x >> 3;
    const int i0 = ks * IB;
    const int os = ot * OT;
    const int b0 = bt * BM;

    const u32 wsm = (u32)__cvta_generic_to_shared(wring);
    const float* wg = w + i0 * O_ + os;   // + i*O_ + col

    // One group = KG slabs = KG*OT floats = 2KB = 128 x 16B chunks; one per thread.
#define PREFW(gsrc, gslot)                                                   \
    {                                                                        \
        int s = tid >> 5;                                                    \
        int off = tid & 31;                                                  \
        cpa16(wsm + (u32)((((gslot) * KG + s) * OT + off * 4) * 4),          \
              wg + ((gsrc) * KG + s) * O_ + off * 4);                        \
        cpa_commit();                                                        \
    }

    // Fill PF groups up front so L2 latency overlaps the prologue.
#pragma unroll
    for (int g = 0; g < PF; ++g) PREFW(g, g);

    // z for this block's i-range (one per thread)
    {
        float q = qz[i0 + tid];
        float pi = 1.0f / (1.0f + expf(-q));
        zsm[tid] = fminf(fmaxf(fmaf(pi, 1.2f, -0.1f), 0.0f), 1.0f);
    }
    __syncthreads();

    // a = x*z - 1, duplicated: row r = tid&15, i-chunk ic = tid>>4 (16 i's each).
    {
        const int r = tid & 15;
        const int ic = tid >> 4;           // 0..7
        const float* xrow = x + (b0 + r) * I_ + i0 + ic * 16;
        const float* zc = zsm + ic * 16;
        float2* ac = (float2*)(aPd + ic * 16 * (2 * BM) + 2 * r);
#pragma unroll
        for (int j4 = 0; j4 < 4; ++j4) {
            float4 xv = *(const float4*)(xrow + j4 * 4);
            float4 zv = *(const float4*)(zc + j4 * 4);
            float v0 = fmaf(xv.x, zv.x, -1.0f);
            float v1 = fmaf(xv.y, zv.y, -1.0f);
            float v2 = fmaf(xv.z, zv.z, -1.0f);
            float v3 = fmaf(xv.w, zv.w, -1.0f);
            ac[(j4 * 4 + 0) * BM] = make_float2(v0, v0);
            ac[(j4 * 4 + 1) * BM] = make_float2(v1, v1);
            ac[(j4 * 4 + 2) * BM] = make_float2(v2, v2);
            ac[(j4 * 4 + 3) * BM] = make_float2(v3, v3);
        }
    }
    __syncthreads();

    // Thread tile: 4 batch rows x 4 o's (2 o-pair accumulators per row).
    // bth is warp-uniform -> a-LDS are full-warp broadcasts.
    const int og = tid & 31;          // o-offset = og*4
    const int bth = (tid >> 5) * 4;   // rows bth..bth+3

    const u64 one2 = 0x3F8000003F800000ULL;
    u64 p[4][2];
#pragma unroll
    for (int r = 0; r < 4; ++r) { p[r][0] = one2; p[r][1] = one2; }

    const float* aB = aPd + 2 * bth;
    const float* wB = wring + og * 4;

#pragma unroll 1
    for (int g = 0; g < NG; ++g) {
        // Race-free protocol (proven R6):
        //   wait_group 5 -> this thread's commits through group g landed;
        //   __syncthreads -> all threads waited => all of group g visible,
        //                    and all threads finished compute through g-1.
        // Prefetch slot (g+PF)&7 last held group g-2: safe to overwrite.
        cpa_wait5();
        __syncthreads();

        const int gslot = g & (RG - 1);
#pragma unroll
        for (int u = 0; u < KG; ++u) {
            const int i = g * KG + u;
            const ulonglong2* ap = (const ulonglong2*)(aB + i * (2 * BM));
            ulonglong2 a01 = ap[0];                                     // (b,b),(b+1,b+1)
            ulonglong2 a23 = ap[1];                                     // (b+2,b+2),(b+3,b+3)
            ulonglong2 wv = *(const ulonglong2*)(wB + (gslot * KG + u) * OT);  // (o,o+1),(o+2,o+3)
            u64 ad[4] = {a01.x, a01.y, a23.x, a23.y};
#pragma unroll
            for (int r = 0; r < 4; ++r) {
                p[r][0] = mul2_(p[r][0], fma2_(ad[r], wv.x, one2));
                p[r][1] = mul2_(p[r][1], fma2_(ad[r], wv.y, one2));
            }
        }

        PREFW((g + PF) & (NG - 1), (g + PF) & (RG - 1));  // tail wraps: fetched, never used
    }

    // Write this split's partial: part_g[ks][b][o..o+3]
    float* pg = part_g + ks * (B_ * O_) + (b0 + bth) * O_ + os + og * 4;
#pragma unroll
    for (int r = 0; r < 4; ++r)
        *(ulonglong2*)(pg + r * O_) = make_ulonglong2(p[r][0], p[r][1]);
}

// ---------------- combine: out = prod of 4 partials ----------------
__global__ __launch_bounds__(256) void l0conj_combine(float* __restrict__ out)
{
    int t = blockIdx.x * 256 + threadIdx.x;   // over B_*O_/4 float4s
    const float4* p0 = (const float4*)part_g;
    const int ts = B_ * O_ / 4;
    float4 a = p0[t];
    float4 b = p0[t + ts];
    float4 c = p0[t + 2 * ts];
    float4 d = p0[t + 3 * ts];
    float4 r;
    r.x = a.x * b.x * c.x * d.x;
    r.y = a.y * b.y * c.y * d.y;
    r.z = a.z * b.z * c.z * d.z;
    r.w = a.w * b.w * c.w * d.w;
    ((float4*)out)[t] = r;
}

extern "C" void kernel_launch(void* const* d_in, const int* in_sizes, int n_in,
                              void* d_out, int out_size) {
    const float* x = nullptr;
    const float* w = nullptr;
    const float* qz = nullptr;
    for (int i = 0; i < n_in; ++i) {
        if (in_sizes[i] == B_ * I_)      x  = (const float*)d_in[i];
        else if (in_sizes[i] == I_ * O_) w  = (const float*)d_in[i];
        else if (in_sizes[i] == I_)      qz = (const float*)d_in[i];
    }
    l0conj_main<<<KSPL * (B_ / BM) * (O_ / OT), NTH>>>(x, w, qz);
    l0conj_combine<<<(B_ * O_ / 4) / 256, 256>>>((float*)d_out);
}